// round 15
// baseline (speedup 1.0000x reference)
#include <cuda_runtime.h>
#include <cuda_bf16.h>
#include <math_constants.h>
#include <cstdint>

#define NB 32
#define NT 512
#define ND 512
#define NV 1024
#define NL 128
#define NS 257      // 2*NL+1
#define PXROW 384   // expanded row: 32 lanes * 12 floats
#define NM (NB*NT)  // 16384 rows

// Scratch (allocation-free per harness rules). g_px padded +4 rows for
// unconditional depth-4 prefetch.
__device__ float g_logits[(size_t)NM * NV];          // 64 MB
__device__ float g_px[(size_t)(NM + 4) * PXROW];     // 25 MB lane-aligned probs
__device__ float2 g_part[(size_t)NM * 32];           // 4 MB per-row/per-warp (max,sumexp)
__device__ float g_loss[NB];
__device__ int   g_cnt;                              // ctc completion counter
__device__ __nv_bfloat16 g_xb[(size_t)NM * ND];      // 16 MB  (x in bf16)
__device__ __nv_bfloat16 g_wt[(size_t)NV * ND];      // 1 MB   (W^T bf16 [V][D])

// ---------------------------------------------------------------------------
// PTX helpers (portable: cp.async sm_80+, ldmatrix sm_75+, mma.bf16 sm_80+)
// ---------------------------------------------------------------------------
__device__ __forceinline__ uint32_t smem_u32(const void* p) {
    uint32_t a;
    asm("{ .reg .u64 t; cvta.to.shared.u64 t, %1; cvt.u32.u64 %0, t; }" : "=r"(a) : "l"(p));
    return a;
}
#define CP_ASYNC16(dst, src) \
    asm volatile("cp.async.cg.shared.global [%0], [%1], 16;" :: "r"(dst), "l"(src))
#define CP_COMMIT() asm volatile("cp.async.commit_group;" ::: "memory")
#define CP_WAIT1()  asm volatile("cp.async.wait_group 1;" ::: "memory")

#define LDSM_X4(r0, r1, r2, r3, addr) \
    asm volatile("ldmatrix.sync.aligned.m8n8.x4.shared.b16 {%0,%1,%2,%3}, [%4];" \
                 : "=r"(r0), "=r"(r1), "=r"(r2), "=r"(r3) : "r"(addr))

#define MMA16816(d, a0, a1, a2, a3, b0, b1) \
    asm volatile("mma.sync.aligned.m16n8k16.row.col.f32.bf16.bf16.f32 " \
                 "{%0,%1,%2,%3}, {%4,%5,%6,%7}, {%8,%9}, {%0,%1,%2,%3};" \
                 : "+f"((d)[0]), "+f"((d)[1]), "+f"((d)[2]), "+f"((d)[3]) \
                 : "r"(a0), "r"(a1), "r"(a2), "r"(a3), "r"(b0), "r"(b1))

// ---------------------------------------------------------------------------
// Kernel 0: fused converts. Blocks [0, 8192): x -> bf16.
//           Blocks [8192, 8704): W[D][V] fp32 -> g_wt[V][D] bf16 (transpose).
// ---------------------------------------------------------------------------
__global__ __launch_bounds__(256) void convert_kernel(const float* __restrict__ x,
                                                      const float* __restrict__ W) {
    if (blockIdx.x < 8192) {
        size_t i = ((size_t)blockIdx.x * 256 + threadIdx.x) * 4;
        float4 v = *(const float4*)(x + i);
        *(__nv_bfloat162*)(g_xb + i) = __floats2bfloat162_rn(v.x, v.y);
        *(__nv_bfloat162*)(g_xb + i + 2) = __floats2bfloat162_rn(v.z, v.w);
    } else {
        __shared__ float t[32][33];
        int blk = blockIdx.x - 8192;          // 0..511
        int tx = threadIdx.x & 31, ty = threadIdx.x >> 5;
        int n0 = (blk & 31) * 32, k0 = (blk >> 5) * 32;
#pragma unroll
        for (int j = 0; j < 32; j += 8)
            t[ty + j][tx] = W[(size_t)(k0 + ty + j) * NV + n0 + tx];
        __syncthreads();
#pragma unroll
        for (int j = 0; j < 32; j += 8)
            g_wt[(size_t)(n0 + ty + j) * ND + k0 + tx] = __float2bfloat16(t[tx][ty + j]);
    }
}

// ---------------------------------------------------------------------------
// Kernel 1: bf16 HMMA GEMM (CTA 128x128, 8 warps, warp tile 64x32).
//   K stages of 64, 3-deep cp.async pipeline, double-buffered register
//   fragments. Epilogue also emits per-warp softmax partials from registers.
// ---------------------------------------------------------------------------
#define KSTAGE 64
#define SROWB 144          // row stride in bytes (128 data + 16 pad)
#define PSTAGES 3
#define STAGE_BYTES (128 * SROWB)               // 18432 B per tile
#define GEMM_SMEM (PSTAGES * STAGE_BYTES * 2)   // 110592 B total

#define LOAD_FRAGS(sl, sAb, sBb, kbyte)                                         \
    do {                                                                        \
        _Pragma("unroll")                                                       \
        for (int mt = 0; mt < 4; mt++)                                          \
            LDSM_X4(af[sl][mt][0], af[sl][mt][1], af[sl][mt][2], af[sl][mt][3], \
                    (sAb) + aoff + mt * 16 * SROWB + (kbyte));                  \
        _Pragma("unroll")                                                       \
        for (int p = 0; p < 2; p++)                                             \
            LDSM_X4(bf[sl][p][0], bf[sl][p][1], bf[sl][p][2], bf[sl][p][3],     \
                    (sBb) + boff + p * 16 * SROWB + (kbyte));                   \
    } while (0)

#define DO_MMAS(sl)                                                             \
    do {                                                                        \
        _Pragma("unroll")                                                       \
        for (int mt = 0; mt < 4; mt++) {                                        \
            _Pragma("unroll")                                                   \
            for (int nt = 0; nt < 4; nt++) {                                    \
                int p = nt >> 1, h = (nt & 1) * 2;                              \
                MMA16816(acc[mt][nt], af[sl][mt][0], af[sl][mt][1],             \
                         af[sl][mt][2], af[sl][mt][3], bf[sl][p][h],            \
                         bf[sl][p][h + 1]);                                     \
            }                                                                   \
        }                                                                       \
    } while (0)

__global__ __launch_bounds__(256) void gemm_hmma_kernel(const float* __restrict__ bias) {
    extern __shared__ __align__(16) char smem[];

    const int tid = threadIdx.x, wid = tid >> 5, lane = tid & 31;
    const int bx = blockIdx.x;           // N tile (0..7)
    const int by = blockIdx.y;           // M tile (0..127)
    const int mBase = by * 128, nBase = bx * 128;
    const int wm = (wid >> 2) * 64;      // warp M offset in tile
    const int wn = (wid & 3) * 32;       // warp N offset in tile

    const __nv_bfloat16* Ag = g_xb + (size_t)mBase * ND;
    const __nv_bfloat16* Bg = g_wt + (size_t)nBase * ND;

    uint32_t sA0 = smem_u32(smem);
    uint32_t sB0 = sA0 + PSTAGES * STAGE_BYTES;

    const int NSTG = ND / KSTAGE;   // 8

    // prologue: stages 0,1
#pragma unroll
    for (int s = 0; s < PSTAGES - 1; s++) {
        const __nv_bfloat16* Ags = Ag + s * KSTAGE;
        const __nv_bfloat16* Bgs = Bg + s * KSTAGE;
        uint32_t sAn = sA0 + s * STAGE_BYTES;
        uint32_t sBn = sB0 + s * STAGE_BYTES;
#pragma unroll
        for (int j = 0; j < 4; j++) {
            int idx = tid + j * 256;
            int r = idx >> 3, c = idx & 7;
            CP_ASYNC16(sAn + r * SROWB + c * 16, Ags + (size_t)r * ND + c * 8);
            CP_ASYNC16(sBn + r * SROWB + c * 16, Bgs + (size_t)r * ND + c * 8);
        }
        CP_COMMIT();
    }

    float acc[4][4][4];
#pragma unroll
    for (int i = 0; i < 4; i++)
#pragma unroll
        for (int j = 0; j < 4; j++)
#pragma unroll
            for (int r = 0; r < 4; r++) acc[i][j][r] = 0.f;

    uint32_t af[2][4][4], bf[2][2][4];   // double-buffered fragments

    uint32_t aoff = (uint32_t)((wm + (lane & 15)) * SROWB + (lane >> 4) * 16);
    uint32_t boff = (uint32_t)((wn + ((lane >> 4) & 1) * 8 + (lane & 7)) * SROWB +
                               ((lane >> 3) & 1) * 16);

#pragma unroll 1
    for (int ks = 0; ks < NSTG; ks++) {
        int buf = ks % PSTAGES;
        CP_WAIT1();             // stage ks arrived
        __syncthreads();        // recycled buffer's readers are done

        int sf = ks + PSTAGES - 1;      // stage to prefetch
        if (sf < NSTG) {
            int nb = sf % PSTAGES;
            const __nv_bfloat16* Ags = Ag + sf * KSTAGE;
            const __nv_bfloat16* Bgs = Bg + sf * KSTAGE;
            uint32_t sAn = sA0 + nb * STAGE_BYTES;
            uint32_t sBn = sB0 + nb * STAGE_BYTES;
#pragma unroll
            for (int j = 0; j < 4; j++) {
                int idx = tid + j * 256;
                int r = idx >> 3, c = idx & 7;
                CP_ASYNC16(sAn + r * SROWB + c * 16, Ags + (size_t)r * ND + c * 8);
                CP_ASYNC16(sBn + r * SROWB + c * 16, Bgs + (size_t)r * ND + c * 8);
            }
        }
        CP_COMMIT();

        uint32_t sAb = sA0 + buf * STAGE_BYTES;
        uint32_t sBb = sB0 + buf * STAGE_BYTES;

        LOAD_FRAGS(0, sAb, sBb, 0);
#pragma unroll
        for (int kk = 0; kk < 4; kk++) {
            int cur = kk & 1;
            if (kk < 3) {
                if (cur) LOAD_FRAGS(0, sAb, sBb, (kk + 1) * 32);
                else     LOAD_FRAGS(1, sAb, sBb, (kk + 1) * 32);
            }
            if (cur) DO_MMAS(1);
            else     DO_MMAS(0);
        }
    }

    // ---------------- epilogue ----------------
    const float* bi = bias + nBase + wn;
    const int pcol = bx * 4 + (wid & 3);         // this warp's partial column
#pragma unroll
    for (int mt = 0; mt < 4; mt++) {
        int r0 = mBase + wm + mt * 16 + (lane >> 2);
        float vA[8], vB[8];
#pragma unroll
        for (int nt = 0; nt < 4; nt++) {
            int c = nt * 8 + (lane & 3) * 2;
            float b0 = bi[c], b1 = bi[c + 1];
            vA[2 * nt]     = acc[mt][nt][0] + b0;
            vA[2 * nt + 1] = acc[mt][nt][1] + b1;
            vB[2 * nt]     = acc[mt][nt][2] + b0;
            vB[2 * nt + 1] = acc[mt][nt][3] + b1;
            *(float2*)(g_logits + (size_t)r0 * NV + nBase + wn + c) =
                make_float2(vA[2 * nt], vA[2 * nt + 1]);
            *(float2*)(g_logits + (size_t)(r0 + 8) * NV + nBase + wn + c) =
                make_float2(vB[2 * nt], vB[2 * nt + 1]);
        }
        float mA = vA[0], mB = vB[0];
#pragma unroll
        for (int j = 1; j < 8; j++) { mA = fmaxf(mA, vA[j]); mB = fmaxf(mB, vB[j]); }
#pragma unroll
        for (int o = 1; o <= 2; o <<= 1) {
            mA = fmaxf(mA, __shfl_xor_sync(0xffffffffu, mA, o));
            mB = fmaxf(mB, __shfl_xor_sync(0xffffffffu, mB, o));
        }
        float sA = 0.f, sB = 0.f;
#pragma unroll
        for (int j = 0; j < 8; j++) { sA += __expf(vA[j] - mA); sB += __expf(vB[j] - mB); }
#pragma unroll
        for (int o = 1; o <= 2; o <<= 1) {
            sA += __shfl_xor_sync(0xffffffffu, sA, o);
            sB += __shfl_xor_sync(0xffffffffu, sB, o);
        }
        if ((lane & 3) == 0) {
            g_part[(size_t)r0 * 32 + pcol] = make_float2(mA, sA);
            g_part[(size_t)(r0 + 8) * 32 + pcol] = make_float2(mB, sB);
        }
    }
}

// ---------------------------------------------------------------------------
// Kernel 2: combine partials + gather -> lane-aligned expanded prob rows.
//   g_px[row][lane*12 + k] = p_ext(s = lane*9 + k) for k<9, 0 for k>=9.
// ---------------------------------------------------------------------------
__global__ __launch_bounds__(256) void combine_kernel(const int* __restrict__ target) {
    __shared__ float sm_plab[8][128];
    int warp = threadIdx.x >> 5, lane = threadIdx.x & 31;
    int row = blockIdx.x * 8 + warp;
    int b = row >> 9;

    float2 ms = g_part[(size_t)row * 32 + lane];
    float m = ms.x;
#pragma unroll
    for (int o = 16; o > 0; o >>= 1) m = fmaxf(m, __shfl_xor_sync(0xffffffffu, m, o));
    float tot = ms.y * __expf(ms.x - m);
#pragma unroll
    for (int o = 16; o > 0; o >>= 1) tot += __shfl_xor_sync(0xffffffffu, tot, o);
    float inv = 1.f / tot;

    const float* lg = g_logits + (size_t)row * NV;
    const int* tg = target + b * NL;
#pragma unroll
    for (int j0 = 0; j0 < NL; j0 += 32) {
        int j = j0 + lane;
        int lab = tg[j];
        sm_plab[warp][j] = __expf(lg[lab] - m) * inv;
    }
    float pblank = __expf(lg[0] - m) * inv;
    __syncwarp();

    float* PX = g_px + (size_t)row * PXROW + lane * 12;
    int s0 = lane * 9;
#pragma unroll
    for (int q = 0; q < 3; q++) {
        float4 o;
        float* op = (float*)&o;
#pragma unroll
        for (int e = 0; e < 4; e++) {
            int k = q * 4 + e;
            int s = s0 + k;
            float v = 0.f;
            if (k < 9 && s < NS)
                v = (s & 1) ? sm_plab[warp][s >> 1] : pblank;
            op[e] = v;
        }
        *(float4*)(PX + q * 4) = o;
    }
}

// ---------------------------------------------------------------------------
// Kernel 3: CTC forward recursion — DUAL-BATCH per warp (ILP hides latency).
//   Each warp runs 2 independent batch recurrences interleaved; branch-free
//   common loop (unroll x4, static every-4 rescale by exact 2^k, depth-4
//   unconditional prefetch), guarded rare tail for unequal TL, hoisted
//   final reduction. Grid = NB/2 warps.
// ---------------------------------------------------------------------------
__device__ __forceinline__ void ctc_step(float* a, const float* skipf, int lane,
                                         float4 pAv, float4 pBv, float pCv) {
    float up1 = __shfl_up_sync(0xffffffffu, a[8], 1);
    float up2 = __shfl_up_sync(0xffffffffu, a[7], 1);
    if (lane == 0) { up1 = 0.f; up2 = 0.f; }
    float n0 = fmaf(skipf[0], up2, a[0] + up1) * pAv.x;
    float n1 = fmaf(skipf[1], up1, a[1] + a[0]) * pAv.y;
    float n2 = fmaf(skipf[2], a[0], a[2] + a[1]) * pAv.z;
    float n3 = fmaf(skipf[3], a[1], a[3] + a[2]) * pAv.w;
    float n4 = fmaf(skipf[4], a[2], a[4] + a[3]) * pBv.x;
    float n5 = fmaf(skipf[5], a[3], a[5] + a[4]) * pBv.y;
    float n6 = fmaf(skipf[6], a[4], a[6] + a[5]) * pBv.z;
    float n7 = fmaf(skipf[7], a[5], a[7] + a[6]) * pBv.w;
    float n8 = fmaf(skipf[8], a[6], a[8] + a[7]) * pCv;
    a[0] = n0; a[1] = n1; a[2] = n2; a[3] = n3; a[4] = n4;
    a[5] = n5; a[6] = n6; a[7] = n7; a[8] = n8;
}

__device__ __forceinline__ void ctc_rescale(float* a, int& escale) {
    float mx = 0.f;
#pragma unroll
    for (int k = 0; k < 9; k++) mx = fmaxf(mx, a[k]);
    unsigned um = __reduce_max_sync(0xffffffffu, __float_as_uint(mx));
    unsigned E = um >> 23;                               // a >= 0
    float sc = __uint_as_float((254u - E) << 23);        // exact 2^(127-E)
    escale += (int)E - 127;
#pragma unroll
    for (int k = 0; k < 9; k++) a[k] *= sc;
}

__device__ __forceinline__ float ctc_final(const float* a, int s0, int send1,
                                           int send2, int escale) {
    float part = 0.f;
#pragma unroll
    for (int k = 0; k < 9; k++) {
        int s = s0 + k;
        part += (s == send1 || s == send2) ? a[k] : 0.f;
    }
#pragma unroll
    for (int o = 16; o > 0; o >>= 1) part += __shfl_xor_sync(0xffffffffu, part, o);
    return (float)escale * 0.6931471805599453f + __logf(part);
}

__global__ __launch_bounds__(32) void ctc_kernel(const int* __restrict__ target,
                                                 const int* __restrict__ in_len,
                                                 const int* __restrict__ tgt_len,
                                                 float* __restrict__ out) {
    int lane = threadIdx.x;
    int s0 = lane * 9;
    int bb[2] = {blockIdx.x * 2, blockIdx.x * 2 + 1};

    float skipf[2][9];
    float a[2][9];
    const float* P[2];
    int TL[2], tl[2], send1[2], send2[2], escale[2];
    float ll[2];

#pragma unroll
    for (int i = 0; i < 2; i++) {
        const int* tg = target + bb[i] * NL;
#pragma unroll
        for (int k = 0; k < 9; k++) {
            int s = s0 + k;
            skipf[i][k] = 0.f;
            if (s >= 3 && s < NS && (s & 1)) {
                int j = (s - 1) >> 1;
                if (tg[j] != tg[j - 1]) skipf[i][k] = 1.f;
            }
        }
        P[i] = g_px + (size_t)bb[i] * NT * PXROW + lane * 12;
        TL[i] = in_len[bb[i]];
        tl[i] = tgt_len[bb[i]];
        send1[i] = 2 * tl[i] - 1;
        send2[i] = 2 * tl[i];
        escale[i] = 0;
        ll[i] = -CUDART_INF_F;

        float4 q0 = *(const float4*)(P[i]);
        float4 q1 = *(const float4*)(P[i] + 4);
        float p8 = P[i][8];
        float v[9] = {q0.x, q0.y, q0.z, q0.w, q1.x, q1.y, q1.z, q1.w, p8};
#pragma unroll
        for (int k = 0; k < 9; k++) {
            int s = s0 + k;
            a[i][k] = (s < 2) ? v[k] : 0.f;
        }
    }

    int Tmin = min(TL[0], TL[1]);

    // prefetch pf[i][u] = p(1+u)
    float4 pA[2][4], pB[2][4];
    float pC[2][4];
#pragma unroll
    for (int i = 0; i < 2; i++)
#pragma unroll
        for (int u = 0; u < 4; u++) {
            const float* Pt = P[i] + (size_t)(u + 1) * PXROW;
            pA[i][u] = *(const float4*)(Pt);
            pB[i][u] = *(const float4*)(Pt + 4);
            pC[i][u] = Pt[8];
        }

    int tb = 1;
#pragma unroll 1
    for (; tb + 3 < Tmin; tb += 4) {
#pragma unroll
        for (int u = 0; u < 4; u++) {
            ctc_step(a[0], skipf[0], lane, pA[0][u], pB[0][u], pC[0][u]);
            ctc_step(a[1], skipf[1], lane, pA[1][u], pB[1][u], pC[1][u]);
            if (u == 3) {
                ctc_rescale(a[0], escale[0]);
                ctc_rescale(a[1], escale[1]);
            }
            // unconditional prefetch of t+4 (array padded by 4 rows)
#pragma unroll
            for (int i = 0; i < 2; i++) {
                const float* Pt = P[i] + (size_t)(tb + u + 4) * PXROW;
                pA[i][u] = *(const float4*)(Pt);
                pB[i][u] = *(const float4*)(Pt + 4);
                pC[i][u] = Pt[8];
            }
        }
    }
    // common remainder: t = tb .. Tmin-1 (at most 3 steps)
#pragma unroll
    for (int u = 0; u < 3; u++) {
        if (tb + u < Tmin) {
            ctc_step(a[0], skipf[0], lane, pA[0][u], pB[0][u], pC[0][u]);
            ctc_step(a[1], skipf[1], lane, pA[1][u], pB[1][u], pC[1][u]);
        }
    }

    // per-batch: finish at Tmin, or continue rare tail to TL[i]-1 then finish
#pragma unroll
    for (int i = 0; i < 2; i++) {
        if (TL[i] > Tmin) {
#pragma unroll 1
            for (int t = Tmin; t < TL[i]; t++) {
                const float* Pt = P[i] + (size_t)t * PXROW;
                float4 qa = *(const float4*)(Pt);
                float4 qb = *(const float4*)(Pt + 4);
                float qc = Pt[8];
                ctc_step(a[i], skipf[i], lane, qa, qb, qc);
                if ((t & 3) == 3) ctc_rescale(a[i], escale[i]);
            }
        }
        ll[i] = ctc_final(a[i], s0, send1[i], send2[i], escale[i]);
    }

    if (lane == 0) {
#pragma unroll
        for (int i = 0; i < 2; i++) {
            float nll = -ll[i];
            if (!(nll < 1e29f)) nll = 0.f;   // zero_infinity (also catches NaN)
            g_loss[bb[i]] = nll / fmaxf((float)tl[i], 1.f);
        }
        __threadfence();
        int prev = atomicAdd(&g_cnt, 1);
        if (prev == NB / 2 - 1) {
            float s = 0.f;
#pragma unroll
            for (int i = 0; i < NB; i++) s += g_loss[i];
            out[0] = s * (1.f / NB);
            g_cnt = 0;   // reset for next graph replay (deterministic)
        }
    }
}

extern "C" void kernel_launch(void* const* d_in, const int* in_sizes, int n_in,
                              void* d_out, int out_size) {
    const float* x = (const float*)d_in[0];        // [B,T,D]
    const float* W = (const float*)d_in[1];        // [D,V]
    const float* bias = (const float*)d_in[2];     // [V]
    const int* target = (const int*)d_in[3];       // [B,L]
    const int* in_len = (const int*)d_in[4];       // [B]
    const int* tgt_len = (const int*)d_in[5];      // [B]

    cudaFuncSetAttribute(gemm_hmma_kernel,
                         cudaFuncAttributeMaxDynamicSharedMemorySize, GEMM_SMEM);

    convert_kernel<<<8192 + 512, 256>>>(x, W);
    {
        dim3 gg(NV / 128, NM / 128);
        gemm_hmma_kernel<<<gg, 256, GEMM_SMEM>>>(bias);
    }
    combine_kernel<<<NM / 8, 256>>>(target);
    ctc_kernel<<<NB / 2, 32>>>(target, in_len, tgt_len, (float*)d_out);
}

// round 16
// speedup vs baseline: 1.3067x; 1.3067x over previous
#include <cuda_runtime.h>
#include <cuda_bf16.h>
#include <math_constants.h>
#include <cstdint>

#define NB 32
#define NT 512
#define ND 512
#define NV 1024
#define NL 128
#define NS 257      // 2*NL+1
#define PXROW 384   // expanded row: 32 lanes * 12 floats
#define NM (NB*NT)  // 16384 rows

// Scratch (allocation-free per harness rules). g_px padded +8 rows for
// unconditional depth-8 prefetch.
__device__ float g_logits[(size_t)NM * NV];          // 64 MB
__device__ float g_px[(size_t)(NM + 8) * PXROW];     // 25 MB lane-aligned probs
__device__ float2 g_part[(size_t)NM * 32];           // 4 MB per-row/per-warp (max,sumexp)
__device__ float g_loss[NB];
__device__ int   g_cnt;                              // ctc completion counter
__device__ __nv_bfloat16 g_xb[(size_t)NM * ND];      // 16 MB  (x in bf16)
__device__ __nv_bfloat16 g_wt[(size_t)NV * ND];      // 1 MB   (W^T bf16 [V][D])

// ---------------------------------------------------------------------------
// PTX helpers (portable: cp.async sm_80+, ldmatrix sm_75+, mma.bf16 sm_80+)
// ---------------------------------------------------------------------------
__device__ __forceinline__ uint32_t smem_u32(const void* p) {
    uint32_t a;
    asm("{ .reg .u64 t; cvta.to.shared.u64 t, %1; cvt.u32.u64 %0, t; }" : "=r"(a) : "l"(p));
    return a;
}
#define CP_ASYNC16(dst, src) \
    asm volatile("cp.async.cg.shared.global [%0], [%1], 16;" :: "r"(dst), "l"(src))
#define CP_COMMIT() asm volatile("cp.async.commit_group;" ::: "memory")
#define CP_WAIT1()  asm volatile("cp.async.wait_group 1;" ::: "memory")

#define LDSM_X4(r0, r1, r2, r3, addr) \
    asm volatile("ldmatrix.sync.aligned.m8n8.x4.shared.b16 {%0,%1,%2,%3}, [%4];" \
                 : "=r"(r0), "=r"(r1), "=r"(r2), "=r"(r3) : "r"(addr))

#define MMA16816(d, a0, a1, a2, a3, b0, b1) \
    asm volatile("mma.sync.aligned.m16n8k16.row.col.f32.bf16.bf16.f32 " \
                 "{%0,%1,%2,%3}, {%4,%5,%6,%7}, {%8,%9}, {%0,%1,%2,%3};" \
                 : "+f"((d)[0]), "+f"((d)[1]), "+f"((d)[2]), "+f"((d)[3]) \
                 : "r"(a0), "r"(a1), "r"(a2), "r"(a3), "r"(b0), "r"(b1))

// ---------------------------------------------------------------------------
// Kernel 0: fused converts. Blocks [0, 8192): x -> bf16.
//           Blocks [8192, 8704): W[D][V] fp32 -> g_wt[V][D] bf16 (transpose).
// ---------------------------------------------------------------------------
__global__ __launch_bounds__(256) void convert_kernel(const float* __restrict__ x,
                                                      const float* __restrict__ W) {
    if (blockIdx.x < 8192) {
        size_t i = ((size_t)blockIdx.x * 256 + threadIdx.x) * 4;
        float4 v = *(const float4*)(x + i);
        *(__nv_bfloat162*)(g_xb + i) = __floats2bfloat162_rn(v.x, v.y);
        *(__nv_bfloat162*)(g_xb + i + 2) = __floats2bfloat162_rn(v.z, v.w);
    } else {
        __shared__ float t[32][33];
        int blk = blockIdx.x - 8192;          // 0..511
        int tx = threadIdx.x & 31, ty = threadIdx.x >> 5;
        int n0 = (blk & 31) * 32, k0 = (blk >> 5) * 32;
#pragma unroll
        for (int j = 0; j < 32; j += 8)
            t[ty + j][tx] = W[(size_t)(k0 + ty + j) * NV + n0 + tx];
        __syncthreads();
#pragma unroll
        for (int j = 0; j < 32; j += 8)
            g_wt[(size_t)(n0 + ty + j) * ND + k0 + tx] = __float2bfloat16(t[tx][ty + j]);
    }
}

// ---------------------------------------------------------------------------
// Kernel 1: bf16 HMMA GEMM (CTA 128x128, 8 warps, warp tile 64x32).
//   K stages of 64, 3-deep cp.async pipeline, double-buffered register
//   fragments. Epilogue also emits per-warp softmax partials from registers.
// ---------------------------------------------------------------------------
#define KSTAGE 64
#define SROWB 144          // row stride in bytes (128 data + 16 pad)
#define PSTAGES 3
#define STAGE_BYTES (128 * SROWB)               // 18432 B per tile
#define GEMM_SMEM (PSTAGES * STAGE_BYTES * 2)   // 110592 B total

#define LOAD_FRAGS(sl, sAb, sBb, kbyte)                                         \
    do {                                                                        \
        _Pragma("unroll")                                                       \
        for (int mt = 0; mt < 4; mt++)                                          \
            LDSM_X4(af[sl][mt][0], af[sl][mt][1], af[sl][mt][2], af[sl][mt][3], \
                    (sAb) + aoff + mt * 16 * SROWB + (kbyte));                  \
        _Pragma("unroll")                                                       \
        for (int p = 0; p < 2; p++)                                             \
            LDSM_X4(bf[sl][p][0], bf[sl][p][1], bf[sl][p][2], bf[sl][p][3],     \
                    (sBb) + boff + p * 16 * SROWB + (kbyte));                   \
    } while (0)

#define DO_MMAS(sl)                                                             \
    do {                                                                        \
        _Pragma("unroll")                                                       \
        for (int mt = 0; mt < 4; mt++) {                                        \
            _Pragma("unroll")                                                   \
            for (int nt = 0; nt < 4; nt++) {                                    \
                int p = nt >> 1, h = (nt & 1) * 2;                              \
                MMA16816(acc[mt][nt], af[sl][mt][0], af[sl][mt][1],             \
                         af[sl][mt][2], af[sl][mt][3], bf[sl][p][h],            \
                         bf[sl][p][h + 1]);                                     \
            }                                                                   \
        }                                                                       \
    } while (0)

__global__ __launch_bounds__(256) void gemm_hmma_kernel(const float* __restrict__ bias) {
    extern __shared__ __align__(16) char smem[];

    const int tid = threadIdx.x, wid = tid >> 5, lane = tid & 31;
    const int bx = blockIdx.x;           // N tile (0..7)
    const int by = blockIdx.y;           // M tile (0..127)
    const int mBase = by * 128, nBase = bx * 128;
    const int wm = (wid >> 2) * 64;      // warp M offset in tile
    const int wn = (wid & 3) * 32;       // warp N offset in tile

    const __nv_bfloat16* Ag = g_xb + (size_t)mBase * ND;
    const __nv_bfloat16* Bg = g_wt + (size_t)nBase * ND;

    uint32_t sA0 = smem_u32(smem);
    uint32_t sB0 = sA0 + PSTAGES * STAGE_BYTES;

    const int NSTG = ND / KSTAGE;   // 8

    // prologue: stages 0,1
#pragma unroll
    for (int s = 0; s < PSTAGES - 1; s++) {
        const __nv_bfloat16* Ags = Ag + s * KSTAGE;
        const __nv_bfloat16* Bgs = Bg + s * KSTAGE;
        uint32_t sAn = sA0 + s * STAGE_BYTES;
        uint32_t sBn = sB0 + s * STAGE_BYTES;
#pragma unroll
        for (int j = 0; j < 4; j++) {
            int idx = tid + j * 256;
            int r = idx >> 3, c = idx & 7;
            CP_ASYNC16(sAn + r * SROWB + c * 16, Ags + (size_t)r * ND + c * 8);
            CP_ASYNC16(sBn + r * SROWB + c * 16, Bgs + (size_t)r * ND + c * 8);
        }
        CP_COMMIT();
    }

    float acc[4][4][4];
#pragma unroll
    for (int i = 0; i < 4; i++)
#pragma unroll
        for (int j = 0; j < 4; j++)
#pragma unroll
            for (int r = 0; r < 4; r++) acc[i][j][r] = 0.f;

    uint32_t af[2][4][4], bf[2][2][4];   // double-buffered fragments

    uint32_t aoff = (uint32_t)((wm + (lane & 15)) * SROWB + (lane >> 4) * 16);
    uint32_t boff = (uint32_t)((wn + ((lane >> 4) & 1) * 8 + (lane & 7)) * SROWB +
                               ((lane >> 3) & 1) * 16);

#pragma unroll 1
    for (int ks = 0; ks < NSTG; ks++) {
        int buf = ks % PSTAGES;
        CP_WAIT1();             // stage ks arrived
        __syncthreads();        // recycled buffer's readers are done

        int sf = ks + PSTAGES - 1;      // stage to prefetch
        if (sf < NSTG) {
            int nb = sf % PSTAGES;
            const __nv_bfloat16* Ags = Ag + sf * KSTAGE;
            const __nv_bfloat16* Bgs = Bg + sf * KSTAGE;
            uint32_t sAn = sA0 + nb * STAGE_BYTES;
            uint32_t sBn = sB0 + nb * STAGE_BYTES;
#pragma unroll
            for (int j = 0; j < 4; j++) {
                int idx = tid + j * 256;
                int r = idx >> 3, c = idx & 7;
                CP_ASYNC16(sAn + r * SROWB + c * 16, Ags + (size_t)r * ND + c * 8);
                CP_ASYNC16(sBn + r * SROWB + c * 16, Bgs + (size_t)r * ND + c * 8);
            }
        }
        CP_COMMIT();

        uint32_t sAb = sA0 + buf * STAGE_BYTES;
        uint32_t sBb = sB0 + buf * STAGE_BYTES;

        LOAD_FRAGS(0, sAb, sBb, 0);
#pragma unroll
        for (int kk = 0; kk < 4; kk++) {
            int cur = kk & 1;
            if (kk < 3) {
                if (cur) LOAD_FRAGS(0, sAb, sBb, (kk + 1) * 32);
                else     LOAD_FRAGS(1, sAb, sBb, (kk + 1) * 32);
            }
            if (cur) DO_MMAS(1);
            else     DO_MMAS(0);
        }
    }

    // ---------------- epilogue ----------------
    const float* bi = bias + nBase + wn;
    const int pcol = bx * 4 + (wid & 3);         // this warp's partial column
#pragma unroll
    for (int mt = 0; mt < 4; mt++) {
        int r0 = mBase + wm + mt * 16 + (lane >> 2);
        float vA[8], vB[8];
#pragma unroll
        for (int nt = 0; nt < 4; nt++) {
            int c = nt * 8 + (lane & 3) * 2;
            float b0 = bi[c], b1 = bi[c + 1];
            vA[2 * nt]     = acc[mt][nt][0] + b0;
            vA[2 * nt + 1] = acc[mt][nt][1] + b1;
            vB[2 * nt]     = acc[mt][nt][2] + b0;
            vB[2 * nt + 1] = acc[mt][nt][3] + b1;
            *(float2*)(g_logits + (size_t)r0 * NV + nBase + wn + c) =
                make_float2(vA[2 * nt], vA[2 * nt + 1]);
            *(float2*)(g_logits + (size_t)(r0 + 8) * NV + nBase + wn + c) =
                make_float2(vB[2 * nt], vB[2 * nt + 1]);
        }
        float mA = vA[0], mB = vB[0];
#pragma unroll
        for (int j = 1; j < 8; j++) { mA = fmaxf(mA, vA[j]); mB = fmaxf(mB, vB[j]); }
#pragma unroll
        for (int o = 1; o <= 2; o <<= 1) {
            mA = fmaxf(mA, __shfl_xor_sync(0xffffffffu, mA, o));
            mB = fmaxf(mB, __shfl_xor_sync(0xffffffffu, mB, o));
        }
        float sA = 0.f, sB = 0.f;
#pragma unroll
        for (int j = 0; j < 8; j++) { sA += __expf(vA[j] - mA); sB += __expf(vB[j] - mB); }
#pragma unroll
        for (int o = 1; o <= 2; o <<= 1) {
            sA += __shfl_xor_sync(0xffffffffu, sA, o);
            sB += __shfl_xor_sync(0xffffffffu, sB, o);
        }
        if ((lane & 3) == 0) {
            g_part[(size_t)r0 * 32 + pcol] = make_float2(mA, sA);
            g_part[(size_t)(r0 + 8) * 32 + pcol] = make_float2(mB, sB);
        }
    }
}

// ---------------------------------------------------------------------------
// Kernel 2: combine partials + gather -> lane-aligned expanded prob rows.
//   g_px[row][lane*12 + k] = p_ext(s = lane*9 + k) for k<9, 0 for k>=9.
// ---------------------------------------------------------------------------
__global__ __launch_bounds__(256) void combine_kernel(const int* __restrict__ target) {
    __shared__ float sm_plab[8][128];
    int warp = threadIdx.x >> 5, lane = threadIdx.x & 31;
    int row = blockIdx.x * 8 + warp;
    int b = row >> 9;

    float2 ms = g_part[(size_t)row * 32 + lane];
    float m = ms.x;
#pragma unroll
    for (int o = 16; o > 0; o >>= 1) m = fmaxf(m, __shfl_xor_sync(0xffffffffu, m, o));
    float tot = ms.y * __expf(ms.x - m);
#pragma unroll
    for (int o = 16; o > 0; o >>= 1) tot += __shfl_xor_sync(0xffffffffu, tot, o);
    float inv = 1.f / tot;

    const float* lg = g_logits + (size_t)row * NV;
    const int* tg = target + b * NL;
#pragma unroll
    for (int j0 = 0; j0 < NL; j0 += 32) {
        int j = j0 + lane;
        int lab = tg[j];
        sm_plab[warp][j] = __expf(lg[lab] - m) * inv;
    }
    float pblank = __expf(lg[0] - m) * inv;
    __syncwarp();

    float* PX = g_px + (size_t)row * PXROW + lane * 12;
    int s0 = lane * 9;
#pragma unroll
    for (int q = 0; q < 3; q++) {
        float4 o;
        float* op = (float*)&o;
#pragma unroll
        for (int e = 0; e < 4; e++) {
            int k = q * 4 + e;
            int s = s0 + k;
            float v = 0.f;
            if (k < 9 && s < NS)
                v = (s & 1) ? sm_plab[warp][s >> 1] : pblank;
            op[e] = v;
        }
        *(float4*)(PX + q * 4) = o;
    }
}

// ---------------------------------------------------------------------------
// Kernel 3: CTC forward recursion, single warp per batch, 9 s per lane.
//   Depth-8 register prefetch ring + running pointer (no per-load IMADs),
//   branch-free 8-unrolled body with static rescale at u==3 and u==7
//   (every-4 cadence, exact 2^k via REDUX max), unconditional prefetch
//   (array padded +8), hoisted final reduction; guarded tail (<=7 steps).
// ---------------------------------------------------------------------------
#define CTC_FSTEP(PF_)                                                          \
    do {                                                                        \
        float up1 = __shfl_up_sync(0xffffffffu, a[8], 1);                       \
        float up2 = __shfl_up_sync(0xffffffffu, a[7], 1);                       \
        if (lane == 0) { up1 = 0.f; up2 = 0.f; }                                \
        float n0 = fmaf(skipf[0], up2, a[0] + up1) * (PF_)[0];                  \
        float n1 = fmaf(skipf[1], up1, a[1] + a[0]) * (PF_)[1];                 \
        float n2 = fmaf(skipf[2], a[0], a[2] + a[1]) * (PF_)[2];                \
        float n3 = fmaf(skipf[3], a[1], a[3] + a[2]) * (PF_)[3];                \
        float n4 = fmaf(skipf[4], a[2], a[4] + a[3]) * (PF_)[4];                \
        float n5 = fmaf(skipf[5], a[3], a[5] + a[4]) * (PF_)[5];                \
        float n6 = fmaf(skipf[6], a[4], a[6] + a[5]) * (PF_)[6];                \
        float n7 = fmaf(skipf[7], a[5], a[7] + a[6]) * (PF_)[7];                \
        float n8 = fmaf(skipf[8], a[6], a[8] + a[7]) * (PF_)[8];                \
        a[0] = n0; a[1] = n1; a[2] = n2; a[3] = n3; a[4] = n4;                  \
        a[5] = n5; a[6] = n6; a[7] = n7; a[8] = n8;                             \
    } while (0)

#define CTC_LOADPF(DST_, PTR_)                                                  \
    do {                                                                        \
        float4 q0_ = *(const float4*)(PTR_);                                    \
        float4 q1_ = *(const float4*)((PTR_) + 4);                              \
        (DST_)[0] = q0_.x; (DST_)[1] = q0_.y; (DST_)[2] = q0_.z;                \
        (DST_)[3] = q0_.w; (DST_)[4] = q1_.x; (DST_)[5] = q1_.y;                \
        (DST_)[6] = q1_.z; (DST_)[7] = q1_.w; (DST_)[8] = (PTR_)[8];            \
    } while (0)

#define CTC_RESCALE()                                                           \
    do {                                                                        \
        float mx = 0.f;                                                         \
        _Pragma("unroll")                                                       \
        for (int k = 0; k < 9; k++) mx = fmaxf(mx, a[k]);                       \
        unsigned um = __reduce_max_sync(0xffffffffu, __float_as_uint(mx));      \
        unsigned E = um >> 23;                                                  \
        float sc = __uint_as_float((254u - E) << 23);                           \
        escale += (int)E - 127;                                                 \
        _Pragma("unroll")                                                       \
        for (int k = 0; k < 9; k++) a[k] *= sc;                                 \
    } while (0)

__global__ __launch_bounds__(32) void ctc_kernel(const int* __restrict__ target,
                                                 const int* __restrict__ in_len,
                                                 const int* __restrict__ tgt_len,
                                                 float* __restrict__ out) {
    int b = blockIdx.x;
    int lane = threadIdx.x;
    int s0 = lane * 9;
    const int* tg = target + b * NL;

    float skipf[9];
#pragma unroll
    for (int k = 0; k < 9; k++) {
        int s = s0 + k;
        skipf[k] = 0.f;
        if (s >= 3 && s < NS && (s & 1)) {
            int j = (s - 1) >> 1;
            if (tg[j] != tg[j - 1]) skipf[k] = 1.f;
        }
    }

    const float* P = g_px + (size_t)b * NT * PXROW + lane * 12;
    int TL = in_len[b];
    int tl = tgt_len[b];
    int send1 = 2 * tl - 1, send2 = 2 * tl;

    float a[9];
    {
        float v[9];
        CTC_LOADPF(v, P);
#pragma unroll
        for (int k = 0; k < 9; k++) {
            int s = s0 + k;
            a[k] = (s < 2) ? v[k] : 0.f;
        }
    }

    int escale = 0;            // true alpha = a * 2^escale
    const float LN2 = 0.6931471805599453f;

    // depth-8 prefetch ring: pf[u] = p(1+u)
    float pf[8][9];
#pragma unroll
    for (int u = 0; u < 8; u++) CTC_LOADPF(pf[u], P + (size_t)(u + 1) * PXROW);
    const float* Pf = P + (size_t)9 * PXROW;   // next row to fetch (t=9)

    int tb = 1;
#pragma unroll 1
    for (; tb + 7 < TL; tb += 8) {
#pragma unroll
        for (int u = 0; u < 8; u++) {
            CTC_FSTEP(pf[u]);
            if (u == 3 || u == 7) CTC_RESCALE();
            CTC_LOADPF(pf[u], Pf);   // unconditional: t+8 (array padded +8)
            Pf += PXROW;
        }
    }
    // remainder: t = tb .. TL-1 (at most 7 steps; no rescale, no prefetch)
#pragma unroll
    for (int u = 0; u < 7; u++) {
        if (tb + u < TL) CTC_FSTEP(pf[u]);
    }

    // final reduction at t = TL-1
    float part = 0.f;
#pragma unroll
    for (int k = 0; k < 9; k++) {
        int s = s0 + k;
        part += (s == send1 || s == send2) ? a[k] : 0.f;
    }
#pragma unroll
    for (int o = 16; o > 0; o >>= 1) part += __shfl_xor_sync(0xffffffffu, part, o);
    float ll = (float)escale * LN2 + __logf(part);

    if (lane == 0) {
        float nll = -ll;
        if (!(nll < 1e29f)) nll = 0.f;   // zero_infinity (also catches NaN)
        g_loss[b] = nll / fmaxf((float)tl, 1.f);
        __threadfence();
        int prev = atomicAdd(&g_cnt, 1);
        if (prev == NB - 1) {
            float s = 0.f;
#pragma unroll
            for (int i = 0; i < NB; i++) s += g_loss[i];
            out[0] = s * (1.f / NB);
            g_cnt = 0;   // reset for next graph replay (deterministic)
        }
    }
}

extern "C" void kernel_launch(void* const* d_in, const int* in_sizes, int n_in,
                              void* d_out, int out_size) {
    const float* x = (const float*)d_in[0];        // [B,T,D]
    const float* W = (const float*)d_in[1];        // [D,V]
    const float* bias = (const float*)d_in[2];     // [V]
    const int* target = (const int*)d_in[3];       // [B,L]
    const int* in_len = (const int*)d_in[4];       // [B]
    const int* tgt_len = (const int*)d_in[5];      // [B]

    cudaFuncSetAttribute(gemm_hmma_kernel,
                         cudaFuncAttributeMaxDynamicSharedMemorySize, GEMM_SMEM);

    convert_kernel<<<8192 + 512, 256>>>(x, W);
    {
        dim3 gg(NV / 128, NM / 128);
        gemm_hmma_kernel<<<gg, 256, GEMM_SMEM>>>(bias);
    }
    combine_kernel<<<NM / 8, 256>>>(target);
    ctc_kernel<<<NB, 32>>>(target, in_len, tgt_len, (float*)d_out);
}